// round 10
// baseline (speedup 1.0000x reference)
#include <cuda_runtime.h>
#include <cuda_fp16.h>
#include <math.h>

// Fixed problem shapes (from setup_inputs)
#define NN   80000
#define NN1  40000
#define NN2  20000
#define NB   16
#define ENC_EMPTY 0x007FFFFFu   // fenc(-inf)

// ---------------- scratch (device globals; no allocation allowed) ----------------
__device__ __align__(16) float    g_agg1[NN * 8];
__device__            unsigned    g_cnt1[NN];
__device__            unsigned    g_x1enc[NN1 * 8];
__device__            int         g_batch1[NN1];
__device__ __align__(16) float    g_x1[NN1 * 8];
__device__ __align__(32) __half   g_xw2h[(size_t)NN1 * 432];  // [N1][27][16] fp16 = 34.5 MB (L2-resident)
__device__ __align__(16) float    g_agg2[NN1 * 16];
__device__            unsigned    g_cnt2[NN1];
__device__            unsigned    g_x2enc[NN2 * 16];
__device__            int         g_batch2[NN2];
__device__ __align__(16) float    g_gsum[NB * 16];
__device__            unsigned    g_gcnt[NB];

// ---------------- helpers ----------------
__device__ __forceinline__ float elu1(float v) { return v > 0.0f ? v : expm1f(v); }

// order-preserving float <-> uint encoding for atomicMax on floats
__device__ __forceinline__ unsigned fenc(float f) {
    unsigned u = __float_as_uint(f);
    return (u & 0x80000000u) ? ~u : (u | 0x80000000u);
}
__device__ __forceinline__ float fdec(unsigned u) {
    return (u & 0x80000000u) ? __uint_as_float(u & 0x7fffffffu) : __uint_as_float(~u);
}

__device__ __forceinline__ __half2 u2h2(unsigned u) {   // well-defined: single 32-bit word
    return *reinterpret_cast<__half2*>(&u);
}

__device__ __forceinline__ void red_add_v4(float* addr, float a, float b, float c, float d) {
    asm volatile("red.global.add.v4.f32 [%0], {%1, %2, %3, %4};"
                 :: "l"(addr), "f"(a), "f"(b), "f"(c), "f"(d) : "memory");
}

// B-spline (degree 1, K=3) fractional parts + base indices from pseudo coords
__device__ __forceinline__ void spline_coords_ldcs(const float* __restrict__ attr, int e,
                                                   float f[3], int i0[3]) {
#pragma unroll
    for (int d = 0; d < 3; d++) {
        float v  = __ldcs(attr + 3 * (size_t)e + d) * 2.0f;   // pseudo * (K-1)
        float fl = floorf(v);
        fl = fminf(fmaxf(fl, 0.0f), 1.0f);                    // clip to [0, K-2]
        i0[d] = (int)fl;
        f[d]  = v - fl;
    }
}

__device__ __forceinline__ void acc_h2(float& a, float& b, unsigned u, float w) {
    __half2 h = u2h2(u);
    float2 fv = __half22float2(h);
    a += w * fv.x; b += w * fv.y;
}

// ---------------- kernels ----------------
__global__ void k_init() {
    int i = blockIdx.x * blockDim.x + threadIdx.x;
    if (i < NN * 8)  g_agg1[i] = 0.0f;
    if (i < NN1 * 16) g_agg2[i] = 0.0f;
    if (i < NN)      g_cnt1[i] = 0u;
    if (i < NN1 * 8) g_x1enc[i] = ENC_EMPTY;
    if (i < NN2 * 16) g_x2enc[i] = ENC_EMPTY;
    if (i < NN1)     { g_batch1[i] = 0; g_cnt2[i] = 0u; }
    if (i < NN2)     g_batch2[i] = 0;
    if (i < NB * 16) g_gsum[i] = 0.0f;
    if (i < NB)      g_gcnt[i] = 0u;
}

// Level-1 edge kernel (fp32): msg[o] = sum_s basis_s * (x[src] . W1[k_s][:,o])
__global__ void k_edge1(const int* __restrict__ ei, const float* __restrict__ attr,
                        const float* __restrict__ x, const float* __restrict__ W1, int E) {
    __shared__ float Ws[27 * 17];   // pad 16->17 to break bank conflicts across k
    for (int j = threadIdx.x; j < 432; j += blockDim.x)
        Ws[(j >> 4) * 17 + (j & 15)] = W1[j];
    __syncthreads();

    int e = blockIdx.x * blockDim.x + threadIdx.x;
    if (e >= E) return;
    int src = __ldcs(ei + e), dst = __ldcs(ei + E + e);

    float f[3]; int i0[3];
    spline_coords_ldcs(attr, e, f, i0);

    float2 xv = *(const float2*)(x + 2 * (size_t)src);

    float msg[8];
#pragma unroll
    for (int o = 0; o < 8; o++) msg[o] = 0.0f;

#pragma unroll
    for (int s = 0; s < 8; s++) {
        int b0 = s & 1, b1 = (s >> 1) & 1, b2 = (s >> 2) & 1;
        float w = (b0 ? f[0] : 1.0f - f[0]) * (b1 ? f[1] : 1.0f - f[1]) * (b2 ? f[2] : 1.0f - f[2]);
        int k = (i0[0] + b0) + 3 * (i0[1] + b1) + 9 * (i0[2] + b2);
        const float* wp = Ws + k * 17;
        float wx = w * xv.x, wy = w * xv.y;
#pragma unroll
        for (int o = 0; o < 8; o++) msg[o] += wx * wp[o] + wy * wp[8 + o];
    }
    float* a = g_agg1 + (size_t)dst * 8;
    red_add_v4(a,     msg[0], msg[1], msg[2], msg[3]);
    red_add_v4(a + 4, msg[4], msg[5], msg[6], msg[7]);
    atomicAdd(&g_cnt1[dst], 1u);
}

// Level-1 node kernel: h = elu(agg/cnt + x@root1 + b1); max-pool into cluster1 bins
__global__ void k_node1(const float* __restrict__ x, const float* __restrict__ root1,
                        const float* __restrict__ b1, const int* __restrict__ batch,
                        const int* __restrict__ cl1, int N) {
    int n = blockIdx.x * blockDim.x + threadIdx.x;
    if (n >= N) return;
    const float4* ar = (const float4*)(g_agg1 + (size_t)n * 8);
    float4 a0 = ar[0], a1 = ar[1];
    float ag[8] = {a0.x, a0.y, a0.z, a0.w, a1.x, a1.y, a1.z, a1.w};
    float inv = 1.0f / fmaxf((float)g_cnt1[n], 1.0f);
    float2 xv = *(const float2*)(x + 2 * (size_t)n);
    int c = cl1[n];
#pragma unroll
    for (int o = 0; o < 8; o++) {
        float h = ag[o] * inv + xv.x * __ldg(root1 + o) + xv.y * __ldg(root1 + 8 + o) + __ldg(b1 + o);
        h = elu1(h);
        atomicMax(&g_x1enc[(size_t)c * 8 + o], fenc(h));
    }
    atomicMax(&g_batch1[c], batch[n]);
}

// Decode x1 + precompute xW2 in fp16: xw2[n1][k][o] = sum_c x1[n1][c]*W2[k][c][o]
// Thread q of each node owns uint4 output chunks u in {q, q+8, ...} (u = 2k+h, 8 halves).
// Warp store pattern: 8 q-lanes -> one contiguous 128B line per node (4 full lines/wavefront).
// Weight rows padded to 144B (9 uint4): q*36 mod 32 distinct -> conflict-free LDS128.
__global__ void k_xw2(const float* __restrict__ W2, int N1) {
    __shared__ uint4   Whs[54 * 9];      // [u][c(8) + pad]
    __shared__ __half2 sxh[32 * 8];      // decoded x1 broadcast half2 per (node, channel)
    __half2* whalf = (__half2*)Whs;
    for (int j = threadIdx.x; j < 1728; j += blockDim.x) {
        int u = j >> 5, c = (j >> 2) & 7, p = j & 3;
        int k = u >> 1, o = (u & 1) * 8 + 2 * p;
        const float* wp = W2 + k * 128 + c * 16 + o;
        whalf[u * 36 + c * 4 + p] = __floats2half2_rn(wp[0], wp[1]);
    }
    int nodeBase = blockIdx.x * 32;
    {
        int node = threadIdx.x >> 3, c = threadIdx.x & 7;
        int n = nodeBase + node;
        if (n < N1) {
            unsigned uenc = g_x1enc[(size_t)n * 8 + c];   // coalesced 1KB per block
            float v = (uenc == ENC_EMPTY) ? 0.0f : fdec(uenc);
            g_x1[(size_t)n * 8 + c] = v;                  // for k_node2's root term
            sxh[threadIdx.x] = __float2half2_rn(v);
        }
    }
    __syncthreads();
    int n1 = nodeBase + (threadIdx.x >> 3);
    int q  = threadIdx.x & 7;
    if (n1 >= N1) return;
    __half2 xh[8];
#pragma unroll
    for (int c = 0; c < 8; c++) xh[c] = sxh[(threadIdx.x & 248) + c];
    uint4* outp = (uint4*)(g_xw2h + (size_t)n1 * 432);
#pragma unroll
    for (int i = 0; i < 7; i++) {
        int u = q + 8 * i;
        if (u >= 54) break;                   // only q>=6 at i==6
        const uint4* wr = Whs + u * 9;
        uint4 w = wr[0];
        __half2 a0 = __hmul2(xh[0], u2h2(w.x));
        __half2 a1 = __hmul2(xh[0], u2h2(w.y));
        __half2 a2 = __hmul2(xh[0], u2h2(w.z));
        __half2 a3 = __hmul2(xh[0], u2h2(w.w));
#pragma unroll
        for (int c = 1; c < 8; c++) {
            w = wr[c];
            a0 = __hfma2(xh[c], u2h2(w.x), a0);
            a1 = __hfma2(xh[c], u2h2(w.y), a1);
            a2 = __hfma2(xh[c], u2h2(w.z), a2);
            a3 = __hfma2(xh[c], u2h2(w.w), a3);
        }
        uint4 r;
        r.x = *(unsigned*)&a0; r.y = *(unsigned*)&a1;
        r.z = *(unsigned*)&a2; r.w = *(unsigned*)&a3;
        outp[u] = r;                          // STG.128, warp-contiguous per node
    }
}

// Level-2 edge kernel: gather fp16 xW2[src2][k_s] (32B/corner, L2-resident),
// weight by basis, fp32 accumulate, scatter to agg2[dst2]
__global__ void k_edge2(const int* __restrict__ ei, const float* __restrict__ attr,
                        const int* __restrict__ cl1, int E) {
    int e = blockIdx.x * blockDim.x + threadIdx.x;
    if (e >= E) return;
    int src = __ldcs(ei + e), dst = __ldcs(ei + E + e);
    int s2 = __ldg(cl1 + src), d2 = __ldg(cl1 + dst);

    float f[3]; int i0[3];
    spline_coords_ldcs(attr, e, f, i0);

    float msg[16];
#pragma unroll
    for (int o = 0; o < 16; o++) msg[o] = 0.0f;

    const __half* basep = g_xw2h + (size_t)s2 * 432;
#pragma unroll
    for (int s = 0; s < 8; s++) {
        int b0 = s & 1, b1 = (s >> 1) & 1, b2 = (s >> 2) & 1;
        float w = (b0 ? f[0] : 1.0f - f[0]) * (b1 ? f[1] : 1.0f - f[1]) * (b2 ? f[2] : 1.0f - f[2]);
        int k = (i0[0] + b0) + 3 * (i0[1] + b1) + 9 * (i0[2] + b2);
        const uint4* p = (const uint4*)(basep + k * 16);
        uint4 v0 = __ldg(p);
        uint4 v1 = __ldg(p + 1);
        acc_h2(msg[0],  msg[1],  v0.x, w);
        acc_h2(msg[2],  msg[3],  v0.y, w);
        acc_h2(msg[4],  msg[5],  v0.z, w);
        acc_h2(msg[6],  msg[7],  v0.w, w);
        acc_h2(msg[8],  msg[9],  v1.x, w);
        acc_h2(msg[10], msg[11], v1.y, w);
        acc_h2(msg[12], msg[13], v1.z, w);
        acc_h2(msg[14], msg[15], v1.w, w);
    }
    float* a = g_agg2 + (size_t)d2 * 16;
    red_add_v4(a,      msg[0],  msg[1],  msg[2],  msg[3]);
    red_add_v4(a + 4,  msg[4],  msg[5],  msg[6],  msg[7]);
    red_add_v4(a + 8,  msg[8],  msg[9],  msg[10], msg[11]);
    red_add_v4(a + 12, msg[12], msg[13], msg[14], msg[15]);
    atomicAdd(&g_cnt2[d2], 1u);
}

// Level-2 node kernel: h2 = elu(agg2/cnt2 + x1@root2 + b2); max-pool into cluster2 bins
__global__ void k_node2(const float* __restrict__ root2, const float* __restrict__ b2,
                        const int* __restrict__ cl2, int N1) {
    int n1 = blockIdx.x * blockDim.x + threadIdx.x;
    if (n1 >= N1) return;
    const float4* ar = (const float4*)(g_agg2 + (size_t)n1 * 16);
    float ag[16];
#pragma unroll
    for (int q = 0; q < 4; q++) {
        float4 v = ar[q];
        ag[q * 4 + 0] = v.x; ag[q * 4 + 1] = v.y; ag[q * 4 + 2] = v.z; ag[q * 4 + 3] = v.w;
    }
    float inv = 1.0f / fmaxf((float)g_cnt2[n1], 1.0f);
    float xv[8];
#pragma unroll
    for (int c = 0; c < 8; c++) xv[c] = g_x1[(size_t)n1 * 8 + c];
    int c2 = cl2[n1];
#pragma unroll
    for (int o = 0; o < 16; o++) {
        float h = ag[o] * inv + __ldg(b2 + o);
#pragma unroll
        for (int c = 0; c < 8; c++) h += xv[c] * __ldg(root2 + c * 16 + o);
        h = elu1(h);
        atomicMax(&g_x2enc[(size_t)c2 * 16 + o], fenc(h));
    }
    atomicMax(&g_batch2[c2], g_batch1[n1]);
}

// Decode x2, per-graph sum/count with shared-memory staging
__global__ void k_pool(int N2) {
    __shared__ float    sg[NB * 16];
    __shared__ unsigned sc[NB];
    if (threadIdx.x < NB * 16) sg[threadIdx.x] = 0.0f;
    if (threadIdx.x < NB)      sc[threadIdx.x] = 0u;
    __syncthreads();
    int n2 = blockIdx.x * blockDim.x + threadIdx.x;
    if (n2 < N2) {
        int b = g_batch2[n2];
#pragma unroll
        for (int o = 0; o < 16; o++) {
            unsigned u = g_x2enc[(size_t)n2 * 16 + o];
            float v = (u == ENC_EMPTY) ? 0.0f : fdec(u);
            atomicAdd(&sg[b * 16 + o], v);
        }
        atomicAdd(&sc[b], 1u);
    }
    __syncthreads();
    if (threadIdx.x < NB * 16) atomicAdd(&g_gsum[threadIdx.x], sg[threadIdx.x]);
    if (threadIdx.x < NB)      atomicAdd(&g_gcnt[threadIdx.x], sc[threadIdx.x]);
}

// Final MLP: g = gsum/cnt; out = elu(elu(g@fc1+b)@fc2+b)
__global__ void k_mlp(const float* __restrict__ fc1_w, const float* __restrict__ fc1_b,
                      const float* __restrict__ fc2_w, const float* __restrict__ fc2_b,
                      float* __restrict__ out) {
    __shared__ float g[NB * 16];
    __shared__ float h[NB * 64];
    for (int idx = threadIdx.x; idx < NB * 16; idx += blockDim.x) {
        int b = idx / 16;
        g[idx] = g_gsum[idx] / fmaxf((float)g_gcnt[b], 1.0f);
    }
    __syncthreads();
    int j = threadIdx.x;   // 64 threads
    if (j < 64) {
#pragma unroll
        for (int b = 0; b < NB; b++) {
            float acc = __ldg(fc1_b + j);
#pragma unroll
            for (int c = 0; c < 16; c++) acc += g[b * 16 + c] * __ldg(fc1_w + c * 64 + j);
            h[b * 64 + j] = elu1(acc);
        }
    }
    __syncthreads();
    if (j < NB) {
        float acc = __ldg(fc2_b);
#pragma unroll
        for (int q = 0; q < 64; q++) acc += h[j * 64 + q] * __ldg(fc2_w + q);
        out[j] = elu1(acc);
    }
}

// ---------------- launch ----------------
extern "C" void kernel_launch(void* const* d_in, const int* in_sizes, int n_in,
                              void* d_out, int out_size) {
    const float* x      = (const float*)d_in[0];
    const int*   ei     = (const int*)  d_in[1];
    const float* attr   = (const float*)d_in[2];
    const int*   batch  = (const int*)  d_in[3];
    const int*   cl1    = (const int*)  d_in[4];
    const int*   cl2    = (const int*)  d_in[5];
    const float* W1     = (const float*)d_in[6];
    const float* root1  = (const float*)d_in[7];
    const float* b1     = (const float*)d_in[8];
    const float* W2     = (const float*)d_in[9];
    const float* root2  = (const float*)d_in[10];
    const float* b2     = (const float*)d_in[11];
    const float* fc1_w  = (const float*)d_in[12];
    const float* fc1_b  = (const float*)d_in[13];
    const float* fc2_w  = (const float*)d_in[14];
    const float* fc2_b  = (const float*)d_in[15];
    float* out = (float*)d_out;

    int N  = in_sizes[3];          // 80000
    int E  = in_sizes[1] / 2;      // 1280000
    int N1 = in_sizes[5];          // 40000
    int N2 = N1 / 2;               // 20000

    const int T = 256;
    k_init <<<(NN * 8 + T - 1) / T, T>>>();
    k_edge1<<<(E + T - 1) / T, T>>>(ei, attr, x, W1, E);
    k_node1<<<(N + T - 1) / T, T>>>(x, root1, b1, batch, cl1, N);
    k_xw2  <<<(N1 + 31) / 32, T>>>(W2, N1);
    k_edge2<<<(E + T - 1) / T, T>>>(ei, attr, cl1, E);
    k_node2<<<(N1 + T - 1) / T, T>>>(root2, b2, cl2, N1);
    k_pool <<<(N2 + T - 1) / T, T>>>(N2);
    k_mlp  <<<1, 64>>>(fc1_w, fc1_b, fc2_w, fc2_b, out);
}

// round 11
// speedup vs baseline: 1.5722x; 1.5722x over previous
#include <cuda_runtime.h>
#include <cuda_fp16.h>
#include <math.h>

// Fixed problem shapes (from setup_inputs)
#define NN   80000
#define NN1  40000
#define NN2  20000
#define NB   16
#define ENC_EMPTY 0x007FFFFFu   // fenc(-inf)

// ---------------- scratch (device globals; no allocation allowed) ----------------
__device__ __align__(16) float    g_agg1[NN * 8];
__device__            unsigned    g_cnt1[NN];
__device__            unsigned    g_x1enc[NN1 * 8];
__device__            int         g_batch1[NN1];
__device__ __align__(16) float    g_x1[NN1 * 8];
__device__ __align__(32) __half   g_xw2h[(size_t)NN1 * 432];  // [N1][27][16] fp16 = 34.5 MB (L2-resident)
__device__ __align__(16) float    g_agg2[NN1 * 16];
__device__            unsigned    g_cnt2[NN1];
__device__            unsigned    g_x2enc[NN2 * 16];
__device__            int         g_batch2[NN2];
__device__ __align__(16) float    g_gsum[NB * 16];
__device__            unsigned    g_gcnt[NB];

// ---------------- helpers ----------------
__device__ __forceinline__ float elu1(float v) { return v > 0.0f ? v : expm1f(v); }

// order-preserving float <-> uint encoding for atomicMax on floats
__device__ __forceinline__ unsigned fenc(float f) {
    unsigned u = __float_as_uint(f);
    return (u & 0x80000000u) ? ~u : (u | 0x80000000u);
}
__device__ __forceinline__ float fdec(unsigned u) {
    return (u & 0x80000000u) ? __uint_as_float(u & 0x7fffffffu) : __uint_as_float(~u);
}

__device__ __forceinline__ __half2 u2h2(unsigned u) {   // well-defined: single 32-bit word
    return *reinterpret_cast<__half2*>(&u);
}

__device__ __forceinline__ void red_add_v4(float* addr, float a, float b, float c, float d) {
    asm volatile("red.global.add.v4.f32 [%0], {%1, %2, %3, %4};"
                 :: "l"(addr), "f"(a), "f"(b), "f"(c), "f"(d) : "memory");
}

// B-spline (degree 1, K=3) fractional parts + base indices from pseudo coords
__device__ __forceinline__ void spline_coords_ldcs(const float* __restrict__ attr, int e,
                                                   float f[3], int i0[3]) {
#pragma unroll
    for (int d = 0; d < 3; d++) {
        float v  = __ldcs(attr + 3 * (size_t)e + d) * 2.0f;   // pseudo * (K-1)
        float fl = floorf(v);
        fl = fminf(fmaxf(fl, 0.0f), 1.0f);                    // clip to [0, K-2]
        i0[d] = (int)fl;
        f[d]  = v - fl;
    }
}

__device__ __forceinline__ void acc_h2(float& a, float& b, unsigned u, float w) {
    __half2 h = u2h2(u);
    float2 fv = __half22float2(h);
    a += w * fv.x; b += w * fv.y;
}

// ---------------- kernels ----------------
__global__ void k_init() {
    int i = blockIdx.x * blockDim.x + threadIdx.x;
    if (i < NN * 8)  g_agg1[i] = 0.0f;
    if (i < NN1 * 16) g_agg2[i] = 0.0f;
    if (i < NN)      g_cnt1[i] = 0u;
    if (i < NN1 * 8) g_x1enc[i] = ENC_EMPTY;
    if (i < NN2 * 16) g_x2enc[i] = ENC_EMPTY;
    if (i < NN1)     { g_batch1[i] = 0; g_cnt2[i] = 0u; }
    if (i < NN2)     g_batch2[i] = 0;
    if (i < NB * 16) g_gsum[i] = 0.0f;
    if (i < NB)      g_gcnt[i] = 0u;
}

// Level-1 edge kernel: msg[o] = sum_s basis_s * (x[src] . W1[k_s][:,o]); scatter-add to agg1[dst]
__global__ void k_edge1(const int* __restrict__ ei, const float* __restrict__ attr,
                        const float* __restrict__ x, const float* __restrict__ W1, int E) {
    __shared__ float Ws[27 * 17];   // pad 16->17 to break bank conflicts across k
    for (int j = threadIdx.x; j < 432; j += blockDim.x)
        Ws[(j >> 4) * 17 + (j & 15)] = W1[j];
    __syncthreads();

    int e = blockIdx.x * blockDim.x + threadIdx.x;
    if (e >= E) return;
    int src = __ldcs(ei + e), dst = __ldcs(ei + E + e);

    float f[3]; int i0[3];
    spline_coords_ldcs(attr, e, f, i0);

    float2 xv = *(const float2*)(x + 2 * (size_t)src);

    float msg[8];
#pragma unroll
    for (int o = 0; o < 8; o++) msg[o] = 0.0f;

#pragma unroll
    for (int s = 0; s < 8; s++) {
        int b0 = s & 1, b1 = (s >> 1) & 1, b2 = (s >> 2) & 1;
        float w = (b0 ? f[0] : 1.0f - f[0]) * (b1 ? f[1] : 1.0f - f[1]) * (b2 ? f[2] : 1.0f - f[2]);
        int k = (i0[0] + b0) + 3 * (i0[1] + b1) + 9 * (i0[2] + b2);
        const float* wp = Ws + k * 17;
        float wx = w * xv.x, wy = w * xv.y;
#pragma unroll
        for (int o = 0; o < 8; o++) msg[o] += wx * wp[o] + wy * wp[8 + o];
    }
    float* a = g_agg1 + (size_t)dst * 8;
    red_add_v4(a,     msg[0], msg[1], msg[2], msg[3]);
    red_add_v4(a + 4, msg[4], msg[5], msg[6], msg[7]);
    atomicAdd(&g_cnt1[dst], 1u);
}

// Level-1 node kernel: h = elu(agg/cnt + x@root1 + b1); max-pool into cluster1 bins.
// Also aggregates cnt1 -> cnt2 (level-2 per-coarse-dst edge counts).
__global__ void k_node1(const float* __restrict__ x, const float* __restrict__ root1,
                        const float* __restrict__ b1, const int* __restrict__ batch,
                        const int* __restrict__ cl1, int N) {
    int n = blockIdx.x * blockDim.x + threadIdx.x;
    if (n >= N) return;
    const float4* ar = (const float4*)(g_agg1 + (size_t)n * 8);
    float4 a0 = ar[0], a1 = ar[1];
    float ag[8] = {a0.x, a0.y, a0.z, a0.w, a1.x, a1.y, a1.z, a1.w};
    unsigned c1 = g_cnt1[n];
    float inv = 1.0f / fmaxf((float)c1, 1.0f);
    float2 xv = *(const float2*)(x + 2 * (size_t)n);
    int c = cl1[n];
#pragma unroll
    for (int o = 0; o < 8; o++) {
        float h = ag[o] * inv + xv.x * __ldg(root1 + o) + xv.y * __ldg(root1 + 8 + o) + __ldg(b1 + o);
        h = elu1(h);
        atomicMax(&g_x1enc[(size_t)c * 8 + o], fenc(h));
    }
    atomicMax(&g_batch1[c], batch[n]);
    if (c1) atomicAdd(&g_cnt2[c], c1);
}

// Decode x1 + precompute xW2 in fp16: xw2[n1][k][o] = sum_c x1[n1][c] * W2[k][c][o]
// 8 threads per node; thread q computes outputs {2q, 2q+1} and stores one half2 per k.
__global__ void k_xw2(const float* __restrict__ W2, int N1) {
    __shared__ float Ws[3456];
    for (int j = threadIdx.x; j < 3456; j += blockDim.x) Ws[j] = W2[j];
    __syncthreads();
    int n1 = blockIdx.x * 32 + (threadIdx.x >> 3);
    int q  = threadIdx.x & 7;
    if (n1 >= N1) return;
    // decode x1 from encoded max-pool (redundant across the 8 threads; L1-resident)
    float xv[8];
#pragma unroll
    for (int c = 0; c < 8; c++) {
        unsigned u = g_x1enc[(size_t)n1 * 8 + c];
        xv[c] = (u == ENC_EMPTY) ? 0.0f : fdec(u);
    }
    if (q < 4)   // write decoded x1 for k_node2's root term
        *(float2*)(g_x1 + (size_t)n1 * 8 + 2 * q) = make_float2(xv[2 * q], xv[2 * q + 1]);

    __half2* outp = (__half2*)(g_xw2h + (size_t)n1 * 432) + q;
    int o0 = 2 * q;
#pragma unroll
    for (int k = 0; k < 27; k++) {
        float acc0 = 0.0f, acc1 = 0.0f;
#pragma unroll
        for (int c = 0; c < 8; c++) {
            acc0 += xv[c] * Ws[k * 128 + c * 16 + o0];
            acc1 += xv[c] * Ws[k * 128 + c * 16 + o0 + 1];
        }
        outp[k * 8] = __floats2half2_rn(acc0, acc1);
    }
}

// Level-2 edge kernel: gather fp16 xW2[src2][k_s] (32B/corner, L2-resident),
// weight by basis, fp32 accumulate, scatter to agg2[dst2]. No count atomic.
__global__ void k_edge2(const int* __restrict__ ei, const float* __restrict__ attr,
                        const int* __restrict__ cl1, int E) {
    int e = blockIdx.x * blockDim.x + threadIdx.x;
    if (e >= E) return;
    int src = __ldcs(ei + e), dst = __ldcs(ei + E + e);
    int s2 = __ldg(cl1 + src), d2 = __ldg(cl1 + dst);

    float f[3]; int i0[3];
    spline_coords_ldcs(attr, e, f, i0);

    float msg[16];
#pragma unroll
    for (int o = 0; o < 16; o++) msg[o] = 0.0f;

    const __half* basep = g_xw2h + (size_t)s2 * 432;
#pragma unroll
    for (int s = 0; s < 8; s++) {
        int b0 = s & 1, b1 = (s >> 1) & 1, b2 = (s >> 2) & 1;
        float w = (b0 ? f[0] : 1.0f - f[0]) * (b1 ? f[1] : 1.0f - f[1]) * (b2 ? f[2] : 1.0f - f[2]);
        int k = (i0[0] + b0) + 3 * (i0[1] + b1) + 9 * (i0[2] + b2);
        const uint4* p = (const uint4*)(basep + k * 16);
        uint4 v0 = __ldg(p);
        uint4 v1 = __ldg(p + 1);
        acc_h2(msg[0],  msg[1],  v0.x, w);
        acc_h2(msg[2],  msg[3],  v0.y, w);
        acc_h2(msg[4],  msg[5],  v0.z, w);
        acc_h2(msg[6],  msg[7],  v0.w, w);
        acc_h2(msg[8],  msg[9],  v1.x, w);
        acc_h2(msg[10], msg[11], v1.y, w);
        acc_h2(msg[12], msg[13], v1.z, w);
        acc_h2(msg[14], msg[15], v1.w, w);
    }
    float* a = g_agg2 + (size_t)d2 * 16;
    red_add_v4(a,      msg[0],  msg[1],  msg[2],  msg[3]);
    red_add_v4(a + 4,  msg[4],  msg[5],  msg[6],  msg[7]);
    red_add_v4(a + 8,  msg[8],  msg[9],  msg[10], msg[11]);
    red_add_v4(a + 12, msg[12], msg[13], msg[14], msg[15]);
}

// Level-2 node kernel: h2 = elu(agg2/cnt2 + x1@root2 + b2); max-pool into cluster2 bins
__global__ void k_node2(const float* __restrict__ root2, const float* __restrict__ b2,
                        const int* __restrict__ cl2, int N1) {
    int n1 = blockIdx.x * blockDim.x + threadIdx.x;
    if (n1 >= N1) return;
    const float4* ar = (const float4*)(g_agg2 + (size_t)n1 * 16);
    float ag[16];
#pragma unroll
    for (int q = 0; q < 4; q++) {
        float4 v = ar[q];
        ag[q * 4 + 0] = v.x; ag[q * 4 + 1] = v.y; ag[q * 4 + 2] = v.z; ag[q * 4 + 3] = v.w;
    }
    float inv = 1.0f / fmaxf((float)g_cnt2[n1], 1.0f);
    float xv[8];
#pragma unroll
    for (int c = 0; c < 8; c++) xv[c] = g_x1[(size_t)n1 * 8 + c];
    int c2 = cl2[n1];
#pragma unroll
    for (int o = 0; o < 16; o++) {
        float h = ag[o] * inv + __ldg(b2 + o);
#pragma unroll
        for (int c = 0; c < 8; c++) h += xv[c] * __ldg(root2 + c * 16 + o);
        h = elu1(h);
        atomicMax(&g_x2enc[(size_t)c2 * 16 + o], fenc(h));
    }
    atomicMax(&g_batch2[c2], g_batch1[n1]);
}

// Decode x2, per-graph sum/count with shared-memory staging
__global__ void k_pool(int N2) {
    __shared__ float    sg[NB * 16];
    __shared__ unsigned sc[NB];
    if (threadIdx.x < NB * 16) sg[threadIdx.x] = 0.0f;
    if (threadIdx.x < NB)      sc[threadIdx.x] = 0u;
    __syncthreads();
    int n2 = blockIdx.x * blockDim.x + threadIdx.x;
    if (n2 < N2) {
        int b = g_batch2[n2];
#pragma unroll
        for (int o = 0; o < 16; o++) {
            unsigned u = g_x2enc[(size_t)n2 * 16 + o];
            float v = (u == ENC_EMPTY) ? 0.0f : fdec(u);
            atomicAdd(&sg[b * 16 + o], v);
        }
        atomicAdd(&sc[b], 1u);
    }
    __syncthreads();
    if (threadIdx.x < NB * 16) atomicAdd(&g_gsum[threadIdx.x], sg[threadIdx.x]);
    if (threadIdx.x < NB)      atomicAdd(&g_gcnt[threadIdx.x], sc[threadIdx.x]);
}

// Final MLP: g = gsum/cnt; out = elu(elu(g@fc1+b)@fc2+b)
__global__ void k_mlp(const float* __restrict__ fc1_w, const float* __restrict__ fc1_b,
                      const float* __restrict__ fc2_w, const float* __restrict__ fc2_b,
                      float* __restrict__ out) {
    __shared__ float g[NB * 16];
    __shared__ float h[NB * 64];
    for (int idx = threadIdx.x; idx < NB * 16; idx += blockDim.x) {
        int b = idx / 16;
        g[idx] = g_gsum[idx] / fmaxf((float)g_gcnt[b], 1.0f);
    }
    __syncthreads();
    int j = threadIdx.x;   // 64 threads
    if (j < 64) {
#pragma unroll
        for (int b = 0; b < NB; b++) {
            float acc = __ldg(fc1_b + j);
#pragma unroll
            for (int c = 0; c < 16; c++) acc += g[b * 16 + c] * __ldg(fc1_w + c * 64 + j);
            h[b * 64 + j] = elu1(acc);
        }
    }
    __syncthreads();
    if (j < NB) {
        float acc = __ldg(fc2_b);
#pragma unroll
        for (int q = 0; q < 64; q++) acc += h[j * 64 + q] * __ldg(fc2_w + q);
        out[j] = elu1(acc);
    }
}

// ---------------- launch ----------------
extern "C" void kernel_launch(void* const* d_in, const int* in_sizes, int n_in,
                              void* d_out, int out_size) {
    const float* x      = (const float*)d_in[0];
    const int*   ei     = (const int*)  d_in[1];
    const float* attr   = (const float*)d_in[2];
    const int*   batch  = (const int*)  d_in[3];
    const int*   cl1    = (const int*)  d_in[4];
    const int*   cl2    = (const int*)  d_in[5];
    const float* W1     = (const float*)d_in[6];
    const float* root1  = (const float*)d_in[7];
    const float* b1     = (const float*)d_in[8];
    const float* W2     = (const float*)d_in[9];
    const float* root2  = (const float*)d_in[10];
    const float* b2     = (const float*)d_in[11];
    const float* fc1_w  = (const float*)d_in[12];
    const float* fc1_b  = (const float*)d_in[13];
    const float* fc2_w  = (const float*)d_in[14];
    const float* fc2_b  = (const float*)d_in[15];
    float* out = (float*)d_out;

    int N  = in_sizes[3];          // 80000
    int E  = in_sizes[1] / 2;      // 1280000
    int N1 = in_sizes[5];          // 40000
    int N2 = N1 / 2;               // 20000

    const int T = 256;
    k_init <<<(NN * 8 + T - 1) / T, T>>>();
    k_edge1<<<(E + T - 1) / T, T>>>(ei, attr, x, W1, E);
    k_node1<<<(N + T - 1) / T, T>>>(x, root1, b1, batch, cl1, N);
    k_xw2  <<<(N1 + 31) / 32, T>>>(W2, N1);
    k_edge2<<<(E + T - 1) / T, T>>>(ei, attr, cl1, E);
    k_node2<<<(N1 + T - 1) / T, T>>>(root2, b2, cl2, N1);
    k_pool <<<(N2 + T - 1) / T, T>>>(N2);
    k_mlp  <<<1, 64>>>(fc1_w, fc1_b, fc2_w, fc2_b, out);
}